// round 5
// baseline (speedup 1.0000x reference)
#include <cuda_runtime.h>
#include <cuda_bf16.h>
#include <cstdint>

// FPQuantizer: per-row absmax clip is the identity, so the reference reduces
// to a pure elementwise flex-fp8 quantizer:
//   bias = 7.15625 (exact bf16)
//   L    = max(floor(log2|x| + bias), 1)
//   s    = 2^(L-12) * 2^(-0.15625)
//   out  = rint(x / s) * s
// Transcendental-free via exponent-field bit tricks:
//   floor(log2|x| + 7.15625) = e + 7 + (mant >= 2^0.84375)
//
// R5: persistent grid-stride kernel with a register double-buffer software
// pipeline: loads for tile i+1 are issued BEFORE the stores of tile i, so
// reads stay in flight across store bursts (steady-state MLP≈8) without
// R4's occupancy collapse. Also removes 16384-CTA launch/drain overhead and
// wave-quantization jitter (grid sized to an integer number of CTAs/SM).

#define QT_THRESH 1.79470907f   // 2^0.84375, fp32-rounded
#define QT_C      0.89735454f   // 2^(-0.15625)
#define QT_CINV   1.11438674f   // 2^(+0.15625)

__device__ __forceinline__ float fpq_quantize(float x) {
    uint32_t b = __float_as_uint(x) & 0x7fffffffu;
    int e = (int)(b >> 23) - 127;
    float mant = __uint_as_float((b & 0x7fffffu) | 0x3f800000u);
    int L = e + 7 + (mant >= QT_THRESH ? 1 : 0);
    L = (L < 1) ? 1 : L;                       // x==0 -> L clamped to 1 -> out 0. Matches ref.
    int k = L - 12;
    float p    = __uint_as_float((uint32_t)(k + 127) << 23);
    float pinv = __uint_as_float((uint32_t)(127 - k) << 23);
    return rintf(x * (pinv * QT_CINV)) * (p * QT_C);  // round-half-even == jnp.round
}

__device__ __forceinline__ float4 fpq_quantize4(float4 v) {
    float4 q;
    q.x = fpq_quantize(v.x);
    q.y = fpq_quantize(v.y);
    q.z = fpq_quantize(v.z);
    q.w = fpq_quantize(v.w);
    return q;
}

#define VPT 4          // float4 vectors per tile per thread
#define THREADS 256

// Grid-stride over tiles of (THREADS*VPT) float4s, double-buffered in regs.
__global__ __launch_bounds__(THREADS) void FPQuantizer_76312978915927_kernel(
    const float4* __restrict__ x, float4* __restrict__ out, int n4)
{
    const int T = THREADS;
    const long tile_elems = (long)T * VPT;
    long pos    = (long)blockIdx.x * tile_elems + threadIdx.x;
    long stride = (long)gridDim.x * tile_elems;

    // fast path: full tiles only (n4 = 16M is divisible by tile_elems=1024)
    long full_end = (long)n4 - (tile_elems - 1);   // tile fully in-bounds if pos < full_end... (pos is thread offset; tile base = pos - threadIdx.x)

    float4 v[VPT];
    bool have = false;
    long cur = -1;

    // prologue: load first tile
    if (pos + (VPT - 1) * T < (long)n4) {
        #pragma unroll
        for (int k = 0; k < VPT; ++k) v[k] = __ldcs(x + pos + k * T);
        have = true;
        cur = pos;
        pos += stride;
    }

    while (have) {
        float4 w[VPT];
        bool have_next = (pos + (VPT - 1) * T < (long)n4);
        if (have_next) {
            // issue next tile's loads BEFORE storing current tile
            #pragma unroll
            for (int k = 0; k < VPT; ++k) w[k] = __ldcs(x + pos + k * T);
        }
        #pragma unroll
        for (int k = 0; k < VPT; ++k)
            __stcs(out + cur + k * T, fpq_quantize4(v[k]));
        if (have_next) {
            #pragma unroll
            for (int k = 0; k < VPT; ++k) v[k] = w[k];
            cur = pos;
            pos += stride;
        }
        have = have_next;
    }

    (void)full_end;
}

// Ragged-remainder kernel (defensive; 8192x8192 has none)
__global__ void FPQuantizer_tail_kernel(const float* __restrict__ x,
                                        float* __restrict__ out,
                                        long start, long n)
{
    long i = start + blockIdx.x * (long)blockDim.x + threadIdx.x;
    if (i < n) out[i] = fpq_quantize(x[i]);
}

extern "C" void kernel_launch(void* const* d_in, const int* in_sizes, int n_in,
                              void* d_out, int out_size)
{
    const float* x = (const float*)d_in[0];
    float* out = (float*)d_out;

    long n  = out_size;
    long n4 = n >> 2;                        // float4 count
    const long tile_elems = (long)THREADS * VPT;   // 1024 float4s per tile

    // Persistent-ish grid: 8 CTAs per SM on 148 SMs (integer waves, no tail
    // quantization), but never more tiles than exist.
    long n_tiles = n4 / tile_elems;          // full tiles
    int grid = (int)((n_tiles < 148L * 8) ? (n_tiles > 0 ? n_tiles : 1) : 148L * 8);

    if (n_tiles > 0) {
        FPQuantizer_76312978915927_kernel<<<grid, THREADS>>>(
            (const float4*)x, (float4*)out, (int)n4);
    }

    // remainder elements not covered by full tiles (none for 8192x8192)
    long covered = n_tiles * tile_elems * 4; // in floats
    long tail = n - covered;
    if (tail > 0) {
        int tblocks = (int)((tail + 255) / 256);
        FPQuantizer_tail_kernel<<<tblocks, 256>>>(x, out, covered, n);
    }
}

// round 6
// speedup vs baseline: 1.0546x; 1.0546x over previous
#include <cuda_runtime.h>
#include <cuda_bf16.h>
#include <cstdint>

// FPQuantizer: per-row absmax clip is the identity, so the reference reduces
// to a pure elementwise flex-fp8 quantizer:
//   bias = 7.15625 (exact bf16)
//   L    = max(floor(log2|x| + bias), 1)
//   s    = 2^(L-12) * 2^(-0.15625)
//   out  = rint(x / s) * s
// Transcendental-free via exponent-field bit tricks:
//   floor(log2|x| + 7.15625) = e + 7 + (mant >= 2^0.84375)
//
// R6: revert to R3 structure (best known: block-strided lane-contiguous
// MLP=4, .cs streaming, 32 regs, high occupancy). R3/R4/R5 all pinned at
// ~6.3 TB/s across wildly different occupancy/MLP configs => chip-level LTS
// sector-throughput ceiling (~6300 B/cyc, path-independent), traffic is
// irreducible (256MB R + 256MB W fp32). Micro-tune only: 512 threads/block
// (half the CTAs, same per-thread work, same occupancy).

#define QT_THRESH 1.79470907f   // 2^0.84375, fp32-rounded
#define QT_C      0.89735454f   // 2^(-0.15625)
#define QT_CINV   1.11438674f   // 2^(+0.15625)

__device__ __forceinline__ float fpq_quantize(float x) {
    uint32_t b = __float_as_uint(x) & 0x7fffffffu;
    int e = (int)(b >> 23) - 127;
    float mant = __uint_as_float((b & 0x7fffffu) | 0x3f800000u);
    int L = e + 7 + (mant >= QT_THRESH ? 1 : 0);
    L = (L < 1) ? 1 : L;                       // x==0 -> L clamped to 1 -> out 0. Matches ref.
    int k = L - 12;
    float p    = __uint_as_float((uint32_t)(k + 127) << 23);
    float pinv = __uint_as_float((uint32_t)(127 - k) << 23);
    return rintf(x * (pinv * QT_CINV)) * (p * QT_C);  // round-half-even == jnp.round
}

__device__ __forceinline__ float4 fpq_quantize4(float4 v) {
    float4 q;
    q.x = fpq_quantize(v.x);
    q.y = fpq_quantize(v.y);
    q.z = fpq_quantize(v.z);
    q.w = fpq_quantize(v.w);
    return q;
}

#define THREADS 512
#define VPT 4   // float4 vectors per thread

// Block processes VPT*THREADS float4s; thread t handles t + k*THREADS within
// the block tile — every memory instruction is warp-contiguous (512B/warp).
__global__ __launch_bounds__(THREADS) void FPQuantizer_76312978915927_kernel(
    const float4* __restrict__ x, float4* __restrict__ out, int n4)
{
    const int T = THREADS;
    int base = blockIdx.x * (T * VPT) + threadIdx.x;

    if (base + (VPT - 1) * T < n4) {
        // front-batch 4 independent, fully-coalesced loads (MLP=4)
        float4 v0 = __ldcs(x + base + 0 * T);
        float4 v1 = __ldcs(x + base + 1 * T);
        float4 v2 = __ldcs(x + base + 2 * T);
        float4 v3 = __ldcs(x + base + 3 * T);
        __stcs(out + base + 0 * T, fpq_quantize4(v0));
        __stcs(out + base + 1 * T, fpq_quantize4(v1));
        __stcs(out + base + 2 * T, fpq_quantize4(v2));
        __stcs(out + base + 3 * T, fpq_quantize4(v3));
    } else {
        // ragged tail block (not hit for 8192x8192: 16M float4s / 2048 exact)
        #pragma unroll
        for (int k = 0; k < VPT; ++k) {
            int i = base + k * T;
            if (i < n4) __stcs(out + i, fpq_quantize4(__ldcs(x + i)));
        }
    }
}

// Scalar tail kernel (defensive; n divisible by 4 here so it won't launch)
__global__ void FPQuantizer_tail_kernel(const float* __restrict__ x,
                                        float* __restrict__ out,
                                        int start, int n)
{
    int i = start + blockIdx.x * blockDim.x + threadIdx.x;
    if (i < n) out[i] = fpq_quantize(x[i]);
}

extern "C" void kernel_launch(void* const* d_in, const int* in_sizes, int n_in,
                              void* d_out, int out_size)
{
    const float* x = (const float*)d_in[0];
    float* out = (float*)d_out;

    int n = out_size;
    int n4 = n >> 2;                        // number of float4 elements
    const int per_block = THREADS * VPT;    // float4s per block

    if (n4 > 0) {
        int blocks = (n4 + per_block - 1) / per_block;
        FPQuantizer_76312978915927_kernel<<<blocks, THREADS>>>(
            (const float4*)x, (float4*)out, n4);
    }
    int tail_start = n4 << 2;
    int tail = n - tail_start;
    if (tail > 0) {
        FPQuantizer_tail_kernel<<<1, 128>>>(x, out, tail_start, n);
    }
}